// round 13
// baseline (speedup 1.0000x reference)
#include <cuda_runtime.h>
#include <cstdint>

// SyntheticTripletLoss closed form: per valid row only
//   pp=<p,p>, tt=<t,t>, pt=<p,t>
//   sim_pn = (pp - pt^2) / max(sqrt(pp - 2pt^2 + pt^2*tt), EPS)
//   loss   = max(MARGIN + sim_pn - pt, 0); mean over valid rows.
//
// R13: single-atomic tail. Streaming is at the LTS cycle floor (R2-R12);
// the only non-streaming cycles left are the reduction tail. Replace
// {partials array + ticket + last-block load loop} with ONE packed u64
// atomicAdd per block: bits[50:61] = completion count, bits[0:50] = block
// loss in 2^24 fixed point. Integer adds are exact+commutative ->
// deterministic. The last block gets the chip total in the atomic's RETURN
// value -- no global re-read at all.

#define MARGIN 0.5f
#define EPS_N 1e-12f

static constexpr int B = 32;
static constexpr int T = 512;
static constexpr int D = 512;
static constexpr int WARPS_PER_BLOCK = 8;
static constexpr int THREADS = WARPS_PER_BLOCK * 32;    // 256
static constexpr int ROWS = B * T;                      // 16384
static constexpr int NBLOCKS = ROWS / WARPS_PER_BLOCK;  // 2048

static constexpr double FIX_SCALE = 16777216.0;         // 2^24
static constexpr int CNT_SHIFT = 50;

__device__ unsigned long long g_acc;   // zero-init; last block resets each run

__global__ __launch_bounds__(THREADS)
void triplet_atomic_kernel(const float* __restrict__ preds,
                           const float* __restrict__ targets,
                           const int* __restrict__ lengths,
                           float* __restrict__ out) {
    const int warp = threadIdx.x >> 5;
    const int lane = threadIdx.x & 31;
    const int row  = blockIdx.x * WARPS_PER_BLOCK + warp;
    const int b    = row >> 9;        // row / T
    const int t    = row & (T - 1);   // row % T

    float loss = 0.0f;

    if (t < __ldg(&lengths[b])) {
        const float4* __restrict__ p4 =
            reinterpret_cast<const float4*>(preds + (size_t)row * D);
        const float4* __restrict__ t4 =
            reinterpret_cast<const float4*>(targets + (size_t)row * D);

        // 512 floats / 32 lanes = 4 float4 per lane per tensor; front-batch
        // all 8 loads for MLP.
        float4 a0 = __ldg(p4 + lane);
        float4 a1 = __ldg(p4 + lane + 32);
        float4 a2 = __ldg(p4 + lane + 64);
        float4 a3 = __ldg(p4 + lane + 96);
        float4 c0 = __ldg(t4 + lane);
        float4 c1 = __ldg(t4 + lane + 32);
        float4 c2 = __ldg(t4 + lane + 64);
        float4 c3 = __ldg(t4 + lane + 96);

        float pp = 0.f, tt = 0.f, pt = 0.f;
        #define ACC(a, c)                                                        \
            pp = fmaf(a.x, a.x, fmaf(a.y, a.y, fmaf(a.z, a.z, fmaf(a.w, a.w, pp)))); \
            tt = fmaf(c.x, c.x, fmaf(c.y, c.y, fmaf(c.z, c.z, fmaf(c.w, c.w, tt)))); \
            pt = fmaf(a.x, c.x, fmaf(a.y, c.y, fmaf(a.z, c.z, fmaf(a.w, c.w, pt))));
        ACC(a0, c0) ACC(a1, c1) ACC(a2, c2) ACC(a3, c3)
        #undef ACC

        #pragma unroll
        for (int off = 16; off; off >>= 1) {
            pp += __shfl_xor_sync(0xffffffffu, pp, off);
            tt += __shfl_xor_sync(0xffffffffu, tt, off);
            pt += __shfl_xor_sync(0xffffffffu, pt, off);
        }

        float pt2  = pt * pt;
        float n2   = fmaxf(pp - 2.0f * pt2 + pt2 * tt, 0.0f);
        float norm = fmaxf(sqrtf(n2), EPS_N);
        loss = fmaxf(MARGIN + (pp - pt2) / norm - pt, 0.0f);
    }

    // ---- block sum (smem) -> single packed atomic ----
    __shared__ float s_warp[WARPS_PER_BLOCK];
    if (lane == 0) s_warp[warp] = loss;
    __syncthreads();

    if (threadIdx.x == 0) {
        float sum = 0.f;
        #pragma unroll
        for (int i = 0; i < WARPS_PER_BLOCK; i++) sum += s_warp[i];

        // 2^24 fixed point via double (exact for this range); loss >= 0.
        unsigned long long contrib =
            (unsigned long long)((double)sum * FIX_SCALE);
        unsigned long long packed = (1ULL << CNT_SHIFT) + contrib;

        unsigned long long old = atomicAdd(&g_acc, packed);

        if ((old >> CNT_SHIFT) == (unsigned long long)(NBLOCKS - 1)) {
            // We are the last block: total is in-register. Exact integer sum
            // -> deterministic.
            unsigned long long total_fix =
                (old + packed) & ((1ULL << CNT_SHIFT) - 1ULL);
            int cnt = 0;
            #pragma unroll
            for (int i = 0; i < B; i++) cnt += __ldg(&lengths[i]);
            out[0] = (float)((double)total_fix / FIX_SCALE / (double)cnt);
            g_acc = 0;   // reset for next graph replay (no later reader races:
                         // every other block's atomic preceded ours)
        }
    }
}

extern "C" void kernel_launch(void* const* d_in, const int* in_sizes, int n_in,
                              void* d_out, int out_size) {
    const float* preds   = (const float*)d_in[0];
    const float* targets = (const float*)d_in[1];
    const int*   lengths = (const int*)d_in[2];
    float* out = (float*)d_out;

    triplet_atomic_kernel<<<NBLOCKS, THREADS>>>(preds, targets, lengths, out);
}